// round 1
// baseline (speedup 1.0000x reference)
#include <cuda_runtime.h>
#include <math.h>

#define B_ 16
#define FH_ 192
#define FW_ 192
#define A_ 9
#define N_ (FH_*FW_*A_)     // 331776 anchors per image
#define P_ 6000             // PRE_NMS_TOPN
#define Q_ 1000             // POST_NMS_TOPN
#define SORT_N 8192
#define NBINS 2048
#define NW_ ((P_ + 31) / 32)   // 188 mask words

// ---------------- scratch (no allocations allowed) ----------------
__device__ unsigned            g_hist[B_][NBINS];
__device__ unsigned            g_cnt[B_];
__device__ int                 g_tb[B_];
__device__ unsigned long long  g_keys[B_][SORT_N];
__device__ float4              g_boxes[B_][P_];

__device__ __forceinline__ int binOf(float s) {
    int b = (int)(s * (float)NBINS);
    return min(max(b, 0), NBINS - 1);
}
__device__ __forceinline__ float clip01(float v) {
    return fminf(fmaxf(v, 0.0f), 1.0f);
}

// ---------------- zero scratch (graph replays reuse it) ----------------
__global__ void zero_kernel() {
    int t = blockIdx.x * blockDim.x + threadIdx.x;
    if (t < B_ * NBINS) ((unsigned*)g_hist)[t] = 0;
    if (t < B_) g_cnt[t] = 0;
}

// ---------------- per-image score histogram ----------------
__global__ void hist_kernel(const float* __restrict__ labels) {
    __shared__ unsigned sh[NBINS];
    int b = blockIdx.y;
    for (int i = threadIdx.x; i < NBINS; i += blockDim.x) sh[i] = 0;
    __syncthreads();
    const float4* lab = (const float4*)(labels + (size_t)b * N_);
    int nvec = N_ / 4;
    for (int v = blockIdx.x * blockDim.x + threadIdx.x; v < nvec; v += gridDim.x * blockDim.x) {
        float4 s = lab[v];
        atomicAdd(&sh[binOf(s.x)], 1u);
        atomicAdd(&sh[binOf(s.y)], 1u);
        atomicAdd(&sh[binOf(s.z)], 1u);
        atomicAdd(&sh[binOf(s.w)], 1u);
    }
    __syncthreads();
    for (int i = threadIdx.x; i < NBINS; i += blockDim.x)
        if (sh[i]) atomicAdd(&g_hist[b][i], sh[i]);
}

// ---------------- threshold bin: smallest bin with suffix count >= P_ ----------------
__global__ void thr_kernel() {
    __shared__ unsigned sh[NBINS];
    int b = blockIdx.x;
    for (int i = threadIdx.x; i < NBINS; i += blockDim.x) sh[i] = g_hist[b][i];
    __syncthreads();
    if (threadIdx.x == 0) {
        unsigned cum = 0;
        int tb = 0;
        for (int i = NBINS - 1; i >= 0; --i) {
            cum += sh[i];
            if (cum >= (unsigned)P_) { tb = i; break; }
        }
        g_tb[b] = tb;
    }
}

// ---------------- compact survivors as 64-bit sort keys ----------------
// key = (~float_bits << 32) | idx  -> ascending sort gives (value desc, idx asc)
// which exactly matches jax.lax.top_k tie-breaking.
__global__ void compact_kernel(const float* __restrict__ labels) {
    int b = blockIdx.y;
    int tb = g_tb[b];
    const float4* lab = (const float4*)(labels + (size_t)b * N_);
    int nvec = N_ / 4;
    for (int v = blockIdx.x * blockDim.x + threadIdx.x; v < nvec; v += gridDim.x * blockDim.x) {
        float4 s4 = lab[v];
        float ss[4] = {s4.x, s4.y, s4.z, s4.w};
        #pragma unroll
        for (int l = 0; l < 4; ++l) {
            float s = ss[l];
            if (binOf(s) >= tb) {
                unsigned pos = atomicAdd(&g_cnt[b], 1u);
                if (pos < SORT_N) {
                    unsigned fb = __float_as_uint(s);
                    unsigned idx = (unsigned)(v * 4 + l);
                    g_keys[b][pos] = (((unsigned long long)(~fb)) << 32) | idx;
                }
            }
        }
    }
}

// ---------------- bitonic sort 8192 keys per image (smem) ----------------
__global__ void sort_kernel() {
    extern __shared__ unsigned long long sk[];
    int b = blockIdx.x;
    unsigned cnt = min(g_cnt[b], (unsigned)SORT_N);
    for (int i = threadIdx.x; i < SORT_N; i += blockDim.x)
        sk[i] = (i < (int)cnt) ? g_keys[b][i] : 0xFFFFFFFFFFFFFFFFULL;
    __syncthreads();
    for (int k = 2; k <= SORT_N; k <<= 1) {
        for (int j = k >> 1; j > 0; j >>= 1) {
            for (int i = threadIdx.x; i < SORT_N; i += blockDim.x) {
                int p = i ^ j;
                if (p > i) {
                    unsigned long long a = sk[i], c = sk[p];
                    bool asc = ((i & k) == 0);
                    if ((a > c) == asc) { sk[i] = c; sk[p] = a; }
                }
            }
            __syncthreads();
        }
    }
    for (int i = threadIdx.x; i < P_; i += blockDim.x) g_keys[b][i] = sk[i];
}

// ---------------- decode the top-P_ boxes only ----------------
__global__ void decode_kernel(const float* __restrict__ deltas,
                              const float* __restrict__ banch) {
    int g = blockIdx.x * blockDim.x + threadIdx.x;
    if (g >= B_ * P_) return;
    int b = g / P_, t = g - b * P_;
    unsigned long long key = g_keys[b][t];
    unsigned idx = (unsigned)key;
    float4 box = make_float4(0.f, 0.f, 0.f, 0.f);
    if (idx < (unsigned)N_) {
        int a = idx % A_;
        int cell = idx / A_;
        int gi = cell / FW_, gj = cell - gi * FW_;
        float cy = ((float)gi + 0.5f) / (float)FH_;
        float cx = ((float)gj + 0.5f) / (float)FW_;
        float b0 = banch[a * 4 + 0], b1 = banch[a * 4 + 1];
        float b2 = banch[a * 4 + 2], b3 = banch[a * 4 + 3];
        // anchors clipped to [0,1] BEFORE decode (matches _generate_anchors)
        float a0 = clip01(cy + b0), a1 = clip01(cx + b1);
        float a2 = clip01(cy + b2), a3 = clip01(cx + b3);
        float4 d = ((const float4*)deltas)[(size_t)b * N_ + idx];
        float d0 = d.x * 0.1f, d1 = d.y * 0.1f, d2 = d.z * 0.2f, d3 = d.w * 0.2f;
        float ah = a2 - a0, aw = a3 - a1;
        float acy = a0 + 0.5f * ah, acx = a1 + 0.5f * aw;
        float h = expf(d2) * ah, w = expf(d3) * aw;
        float ncy = d0 * ah + acy, ncx = d1 * aw + acx;
        box.x = clip01(ncy - 0.5f * h);
        box.y = clip01(ncx - 0.5f * w);
        box.z = clip01(ncy + 0.5f * h);
        box.w = clip01(ncx + 0.5f * w);
    }
    g_boxes[b][t] = box;
}

// ---------------- sequential greedy NMS, one block per image ----------------
// Candidates are score-sorted, so argmax == first alive index. A 6016-bit
// alive mask lives in smem; thread 0 finds the next selection, all threads
// suppress j>i by IoU > 0.7.
__global__ void nms_kernel(float4* __restrict__ out) {
    extern __shared__ char smem[];
    float4*   sbox  = (float4*)smem;                       // P_ * 16 bytes
    float*    sarea = (float*)(smem + (size_t)P_ * 16);    // P_ * 4 bytes
    unsigned* alive = (unsigned*)(smem + (size_t)P_ * 20); // NW_ * 4 bytes
    __shared__ int s_cur;

    int b = blockIdx.x;
    int tid = threadIdx.x, nt = blockDim.x;

    for (int i = tid; i < P_; i += nt) {
        float4 bx = g_boxes[b][i];
        sbox[i] = bx;
        sarea[i] = fmaxf(bx.z - bx.x, 0.f) * fmaxf(bx.w - bx.y, 0.f);
    }
    for (int w = tid; w < NW_; w += nt) {
        int lo = w * 32;
        unsigned m = 0xFFFFFFFFu;
        if (lo + 32 > P_) m = (1u << (P_ - lo)) - 1u;
        alive[w] = m;
    }
    __syncthreads();

    int outc = 0;
    int sw = 0; // thread-0 private search cursor
    float4* orow = out + (size_t)b * Q_;

    for (int it = 0; it < Q_; ++it) {
        if (tid == 0) {
            int found = -1;
            for (int w = sw; w < NW_; ++w) {
                unsigned v = alive[w];
                if (v) {
                    int bp = __ffs(v) - 1;
                    found = w * 32 + bp;
                    alive[w] = v & (v - 1u); // clear selected bit
                    sw = w;
                    break;
                }
            }
            s_cur = found;
        }
        __syncthreads();
        int i = s_cur;
        if (i < 0) break;

        float4 bi = sbox[i];
        float  ai = sarea[i];
        if (tid == 0) orow[outc] = bi;

        for (int j = i + 1 + tid; j < P_; j += nt) {
            unsigned wv = alive[j >> 5];
            if ((wv >> (j & 31)) & 1u) {
                float4 bj = sbox[j];
                float yy1 = fmaxf(bi.x, bj.x);
                float xx1 = fmaxf(bi.y, bj.y);
                float yy2 = fminf(bi.z, bj.z);
                float xx2 = fminf(bi.w, bj.w);
                float inter = fmaxf(yy2 - yy1, 0.f) * fmaxf(xx2 - xx1, 0.f);
                float iou = inter / (ai + sarea[j] - inter + 1e-8f);
                if (iou > 0.7f)
                    atomicAnd(&alive[j >> 5], ~(1u << (j & 31)));
            }
        }
        outc++;
        __syncthreads();
    }

    float4 z = make_float4(0.f, 0.f, 0.f, 0.f);
    for (int r = outc + tid; r < Q_; r += nt) orow[r] = z;
}

// ---------------- launch ----------------
extern "C" void kernel_launch(void* const* d_in, const int* in_sizes, int n_in,
                              void* d_out, int out_size) {
    const float* deltas = (const float*)d_in[0]; // (B,FH,FW,36)
    const float* labels = (const float*)d_in[1]; // (B,FH,FW,9)
    const float* banch  = (const float*)d_in[2]; // (9,4)
    float4* out = (float4*)d_out;                // (B,1000,4) float32

    (void)in_sizes; (void)n_in; (void)out_size;

    cudaFuncSetAttribute(sort_kernel, cudaFuncAttributeMaxDynamicSharedMemorySize,
                         SORT_N * (int)sizeof(unsigned long long));
    cudaFuncSetAttribute(nms_kernel, cudaFuncAttributeMaxDynamicSharedMemorySize,
                         P_ * 20 + NW_ * 4 + 16);

    zero_kernel<<<64, 512>>>();
    hist_kernel<<<dim3(36, B_), 256>>>(labels);
    thr_kernel<<<B_, 256>>>();
    compact_kernel<<<dim3(36, B_), 256>>>(labels);
    sort_kernel<<<B_, 1024, SORT_N * sizeof(unsigned long long)>>>();
    decode_kernel<<<(B_ * P_ + 255) / 256, 256>>>(deltas, banch);
    nms_kernel<<<B_, 512, P_ * 20 + NW_ * 4 + 16>>>(out);
}

// round 2
// speedup vs baseline: 4.1351x; 4.1351x over previous
#include <cuda_runtime.h>
#include <math.h>

#define B_ 16
#define FH_ 192
#define FW_ 192
#define A_ 9
#define N_ (FH_*FW_*A_)     // 331776 anchors per image
#define P_ 6000             // PRE_NMS_TOPN
#define Q_ 1000             // POST_NMS_TOPN
#define SORT_N 8192
#define NBINS 2048
#define NW_ ((P_ + 31) / 32)   // 188 mask words per row
#define RT_ 128                // mask tile rows
#define CT_ 128                // mask tile cols (4 words)

// ---------------- scratch (no allocations allowed) ----------------
__device__ unsigned            g_hist[B_][NBINS];
__device__ unsigned            g_cnt[B_];
__device__ int                 g_tb[B_];
__device__ unsigned long long  g_keys[B_][SORT_N];
__device__ float4              g_boxes[B_][P_];
__device__ unsigned            g_mask[B_][P_][NW_];   // ~72 MB, static

__device__ __forceinline__ int binOf(float s) {
    int b = (int)(s * (float)NBINS);
    return min(max(b, 0), NBINS - 1);
}
__device__ __forceinline__ float clip01(float v) {
    return fminf(fmaxf(v, 0.0f), 1.0f);
}

// ---------------- zero scratch (graph replays reuse it) ----------------
__global__ void zero_kernel() {
    int t = blockIdx.x * blockDim.x + threadIdx.x;
    if (t < B_ * NBINS) ((unsigned*)g_hist)[t] = 0;
    if (t < B_) g_cnt[t] = 0;
}

// ---------------- per-image score histogram ----------------
__global__ void hist_kernel(const float* __restrict__ labels) {
    __shared__ unsigned sh[NBINS];
    int b = blockIdx.y;
    for (int i = threadIdx.x; i < NBINS; i += blockDim.x) sh[i] = 0;
    __syncthreads();
    const float4* lab = (const float4*)(labels + (size_t)b * N_);
    int nvec = N_ / 4;
    for (int v = blockIdx.x * blockDim.x + threadIdx.x; v < nvec; v += gridDim.x * blockDim.x) {
        float4 s = lab[v];
        atomicAdd(&sh[binOf(s.x)], 1u);
        atomicAdd(&sh[binOf(s.y)], 1u);
        atomicAdd(&sh[binOf(s.z)], 1u);
        atomicAdd(&sh[binOf(s.w)], 1u);
    }
    __syncthreads();
    for (int i = threadIdx.x; i < NBINS; i += blockDim.x)
        if (sh[i]) atomicAdd(&g_hist[b][i], sh[i]);
}

// ---------------- threshold bin: smallest bin with suffix count >= P_ ----------------
__global__ void thr_kernel() {
    __shared__ unsigned sh[NBINS];
    int b = blockIdx.x;
    for (int i = threadIdx.x; i < NBINS; i += blockDim.x) sh[i] = g_hist[b][i];
    __syncthreads();
    if (threadIdx.x == 0) {
        unsigned cum = 0;
        int tb = 0;
        for (int i = NBINS - 1; i >= 0; --i) {
            cum += sh[i];
            if (cum >= (unsigned)P_) { tb = i; break; }
        }
        g_tb[b] = tb;
    }
}

// ---------------- compact survivors as 64-bit sort keys ----------------
// key = (~float_bits << 32) | idx  -> ascending sort gives (value desc, idx asc)
__global__ void compact_kernel(const float* __restrict__ labels) {
    int b = blockIdx.y;
    int tb = g_tb[b];
    const float4* lab = (const float4*)(labels + (size_t)b * N_);
    int v = blockIdx.x * blockDim.x + threadIdx.x;
    if (v >= N_ / 4) return;
    float4 s4 = lab[v];
    float ss[4] = {s4.x, s4.y, s4.z, s4.w};
    #pragma unroll
    for (int l = 0; l < 4; ++l) {
        float s = ss[l];
        if (binOf(s) >= tb) {
            unsigned pos = atomicAdd(&g_cnt[b], 1u);
            if (pos < SORT_N) {
                unsigned fb = __float_as_uint(s);
                unsigned idx = (unsigned)(v * 4 + l);
                g_keys[b][pos] = (((unsigned long long)(~fb)) << 32) | idx;
            }
        }
    }
}

// ---------------- bitonic sort 8192 keys per image (smem) ----------------
__global__ void sort_kernel() {
    extern __shared__ unsigned long long sk[];
    int b = blockIdx.x;
    unsigned cnt = min(g_cnt[b], (unsigned)SORT_N);
    for (int i = threadIdx.x; i < SORT_N; i += blockDim.x)
        sk[i] = (i < (int)cnt) ? g_keys[b][i] : 0xFFFFFFFFFFFFFFFFULL;
    __syncthreads();
    for (int k = 2; k <= SORT_N; k <<= 1) {
        for (int j = k >> 1; j > 0; j >>= 1) {
            for (int i = threadIdx.x; i < SORT_N; i += blockDim.x) {
                int p = i ^ j;
                if (p > i) {
                    unsigned long long a = sk[i], c = sk[p];
                    bool asc = ((i & k) == 0);
                    if ((a > c) == asc) { sk[i] = c; sk[p] = a; }
                }
            }
            __syncthreads();
        }
    }
    for (int i = threadIdx.x; i < P_; i += blockDim.x) g_keys[b][i] = sk[i];
}

// ---------------- decode the top-P_ boxes only ----------------
__global__ void decode_kernel(const float* __restrict__ deltas,
                              const float* __restrict__ banch) {
    int g = blockIdx.x * blockDim.x + threadIdx.x;
    if (g >= B_ * P_) return;
    int b = g / P_, t = g - b * P_;
    unsigned long long key = g_keys[b][t];
    unsigned idx = (unsigned)key;
    float4 box = make_float4(0.f, 0.f, 0.f, 0.f);
    if (idx < (unsigned)N_) {
        int a = idx % A_;
        int cell = idx / A_;
        int gi = cell / FW_, gj = cell - gi * FW_;
        float cy = ((float)gi + 0.5f) / (float)FH_;
        float cx = ((float)gj + 0.5f) / (float)FW_;
        float b0 = banch[a * 4 + 0], b1 = banch[a * 4 + 1];
        float b2 = banch[a * 4 + 2], b3 = banch[a * 4 + 3];
        float a0 = clip01(cy + b0), a1 = clip01(cx + b1);
        float a2 = clip01(cy + b2), a3 = clip01(cx + b3);
        float4 d = ((const float4*)deltas)[(size_t)b * N_ + idx];
        float d0 = d.x * 0.1f, d1 = d.y * 0.1f, d2 = d.z * 0.2f, d3 = d.w * 0.2f;
        float ah = a2 - a0, aw = a3 - a1;
        float acy = a0 + 0.5f * ah, acx = a1 + 0.5f * aw;
        float h = expf(d2) * ah, w = expf(d3) * aw;
        float ncy = d0 * ah + acy, ncx = d1 * aw + acx;
        box.x = clip01(ncy - 0.5f * h);
        box.y = clip01(ncx - 0.5f * w);
        box.z = clip01(ncy + 0.5f * h);
        box.w = clip01(ncx + 0.5f * w);
    }
    g_boxes[b][t] = box;
}

// ---------------- pairwise suppression bitmask (upper triangle) ----------------
// Thread = one row i; column tile of 128 boxes in smem SoA so every read is a
// warp broadcast. Division avoided except in a ~1e-6 borderline window where we
// replay the reference's exact inter/denom > 0.7 comparison.
__global__ void mask_kernel() {
    int b = blockIdx.z;
    int rowBase = blockIdx.y * RT_;
    int colBase = blockIdx.x * CT_;
    if (colBase + CT_ <= rowBase) return;   // entirely j <= i: never read

    __shared__ float sy1[CT_], sx1[CT_], sy2[CT_], sx2[CT_], sar[CT_];
    int tid = threadIdx.x;
    {
        int j = colBase + tid;
        float4 bj = (j < P_) ? g_boxes[b][j] : make_float4(0.f, 0.f, 0.f, 0.f);
        sy1[tid] = bj.x; sx1[tid] = bj.y; sy2[tid] = bj.z; sx2[tid] = bj.w;
        sar[tid] = fmaxf(bj.z - bj.x, 0.f) * fmaxf(bj.w - bj.y, 0.f);
    }
    __syncthreads();

    int i = rowBase + tid;
    if (i >= P_) return;
    float4 bi = g_boxes[b][i];
    float ai = fmaxf(bi.z - bi.x, 0.f) * fmaxf(bi.w - bi.y, 0.f);
    int wbase = colBase >> 5;

    #pragma unroll
    for (int cw = 0; cw < CT_ / 32; ++cw) {
        unsigned bits = 0;
        #pragma unroll 8
        for (int jj = 0; jj < 32; ++jj) {
            int jl = cw * 32 + jj;
            int j  = colBase + jl;
            float yy1 = fmaxf(bi.x, sy1[jl]);
            float xx1 = fmaxf(bi.y, sx1[jl]);
            float yy2 = fminf(bi.z, sy2[jl]);
            float xx2 = fminf(bi.w, sx2[jl]);
            float inter = fmaxf(yy2 - yy1, 0.f) * fmaxf(xx2 - xx1, 0.f);
            float denom = ai + sar[jl] - inter + 1e-8f;
            float t = 0.7f * denom;
            bool sup = inter > t;
            if (fabsf(inter - t) < 1e-6f * denom)   // borderline: exact replay
                sup = (inter / denom) > 0.7f;
            if (sup && j > i && j < P_) bits |= (1u << jj);
        }
        int w = wbase + cw;
        if (w < NW_) g_mask[b][i][w] = bits;
    }
}

// ---------------- sequential greedy reduce: one warp per image ----------------
// removed bitset lives in 6 regs/lane (lane l owns words k*32+l). Per selection:
// one coalesced 188-word row load (L2-resident) OR'd into removed.
__global__ void nms_reduce_kernel(float4* __restrict__ out) {
    int b = blockIdx.x;
    int lane = threadIdx.x;
    const unsigned FULL = 0xFFFFFFFFu;

    unsigned removed[6];
    #pragma unroll
    for (int k = 0; k < 6; ++k) removed[k] = 0u;

    float4* orow = out + (size_t)b * Q_;
    int outc = 0;

    for (int w = 0; w < NW_ && outc < Q_; ++w) {
        unsigned valid = (w == NW_ - 1) ? ((1u << (P_ - (NW_ - 1) * 32)) - 1u) : FULL;
        unsigned rw = __shfl_sync(FULL, removed[w >> 5], w & 31);
        unsigned alive = ~rw & valid;
        while (alive) {
            int bit = __ffs(alive) - 1;
            int i = w * 32 + bit;
            if (lane == 0) orow[outc] = g_boxes[b][i];
            outc++;

            const unsigned* row = &g_mask[b][i][0];
            unsigned rloc[6];
            #pragma unroll
            for (int k = 0; k < 6; ++k) {
                int wi = k * 32 + lane;
                rloc[k] = (wi < NW_ && wi >= w) ? row[wi] : 0u;
                removed[k] |= rloc[k];
            }
            unsigned roww = __shfl_sync(FULL, rloc[w >> 5], w & 31);
            alive &= ~roww;
            alive &= (bit < 31) ? (FULL << (bit + 1)) : 0u;
            if (outc >= Q_) break;
        }
    }

    float4 z = make_float4(0.f, 0.f, 0.f, 0.f);
    for (int r = outc + lane; r < Q_; r += 32) orow[r] = z;
}

// ---------------- launch ----------------
extern "C" void kernel_launch(void* const* d_in, const int* in_sizes, int n_in,
                              void* d_out, int out_size) {
    const float* deltas = (const float*)d_in[0]; // (B,FH,FW,36)
    const float* labels = (const float*)d_in[1]; // (B,FH,FW,9)
    const float* banch  = (const float*)d_in[2]; // (9,4)
    float4* out = (float4*)d_out;                // (B,1000,4) float32

    (void)in_sizes; (void)n_in; (void)out_size;

    cudaFuncSetAttribute(sort_kernel, cudaFuncAttributeMaxDynamicSharedMemorySize,
                         SORT_N * (int)sizeof(unsigned long long));

    zero_kernel<<<64, 512>>>();
    hist_kernel<<<dim3(36, B_), 256>>>(labels);
    thr_kernel<<<B_, 256>>>();
    compact_kernel<<<dim3((N_ / 4 + 255) / 256, B_), 256>>>(labels);
    sort_kernel<<<B_, 1024, SORT_N * sizeof(unsigned long long)>>>();
    decode_kernel<<<(B_ * P_ + 255) / 256, 256>>>(deltas, banch);

    int rowTiles = (P_ + RT_ - 1) / RT_;   // 47
    int colTiles = (NW_ * 32 + CT_ - 1) / CT_;  // 47
    mask_kernel<<<dim3(colTiles, rowTiles, B_), RT_>>>();
    nms_reduce_kernel<<<B_, 32>>>(out);
}